// round 12
// baseline (speedup 1.0000x reference)
#include <cuda_runtime.h>
#include <cuda_bf16.h>
#include <stdint.h>
#include <math.h>

#define S_LEN 2048
#define HID   3584
#define NHQ   28
#define NKV   4
#define DH    128
#define DKV   (NKV * DH)   // 512
#define N_REP (NHQ / NKV)  // 7

// ---------------- scratch (__device__ globals; no allocs allowed) ----------
__device__ float g_P1[S_LEN * HID];    // split-K partial for O projection

__device__ __nv_bfloat16 g_hs_h[S_LEN * HID],  g_hs_l[S_LEN * HID];
__device__ __nv_bfloat16 g_ao_h[S_LEN * HID],  g_ao_l[S_LEN * HID];
__device__ __nv_bfloat16 g_wq_h[HID * HID],    g_wq_l[HID * HID];
__device__ __nv_bfloat16 g_wo_h[HID * HID],    g_wo_l[HID * HID];
__device__ __nv_bfloat16 g_wk_h[DKV * HID],    g_wk_l[DKV * HID];
__device__ __nv_bfloat16 g_wv_h[DKV * HID],    g_wv_l[DKV * HID];

// post-RoPE bf16 splits for attention
__device__ __nv_bfloat16 g_q_h[S_LEN * HID],  g_q_l[S_LEN * HID];
__device__ __nv_bfloat16 g_k_h[S_LEN * DKV],  g_k_l[S_LEN * DKV];
__device__ __nv_bfloat16 g_v_h[S_LEN * DKV],  g_v_l[S_LEN * DKV];

// ---------------- PTX helpers ---------------------------------------------
__device__ __forceinline__ uint32_t smem_u32(const void* p) {
    uint32_t a;
    asm("{ .reg .u64 t; cvta.to.shared.u64 t, %1; cvt.u32.u64 %0, t; }"
        : "=r"(a) : "l"(p));
    return a;
}
__device__ __forceinline__ void cp_async16(uint32_t dst, const void* src) {
    asm volatile("cp.async.cg.shared.global [%0], [%1], 16;\n"
                 :: "r"(dst), "l"(src) : "memory");
}
__device__ __forceinline__ void cp_commit() {
    asm volatile("cp.async.commit_group;" ::: "memory");
}
__device__ __forceinline__ void ldsm4(uint32_t* r, uint32_t addr) {
    asm volatile("ldmatrix.sync.aligned.m8n8.x4.shared.b16 {%0,%1,%2,%3}, [%4];\n"
                 : "=r"(r[0]), "=r"(r[1]), "=r"(r[2]), "=r"(r[3]) : "r"(addr));
}
__device__ __forceinline__ void ldsm4t(uint32_t* r, uint32_t addr) {
    asm volatile("ldmatrix.sync.aligned.m8n8.x4.trans.shared.b16 {%0,%1,%2,%3}, [%4];\n"
                 : "=r"(r[0]), "=r"(r[1]), "=r"(r[2]), "=r"(r[3]) : "r"(addr));
}
__device__ __forceinline__ void mma16816(float* c, const uint32_t* a,
                                         const uint32_t* b) {
    asm volatile(
        "mma.sync.aligned.m16n8k16.row.col.f32.bf16.bf16.f32 "
        "{%0,%1,%2,%3}, {%4,%5,%6,%7}, {%8,%9}, {%0,%1,%2,%3};\n"
        : "+f"(c[0]), "+f"(c[1]), "+f"(c[2]), "+f"(c[3])
        : "r"(a[0]), "r"(a[1]), "r"(a[2]), "r"(a[3]), "r"(b[0]), "r"(b[1]));
}
__device__ __forceinline__ float ex2f(float x) {
    float y;
    asm("ex2.approx.ftz.f32 %0, %1;" : "=f"(y) : "f"(x));
    return y;
}
__device__ __forceinline__ uint32_t packbf(float a, float b) {
    __nv_bfloat162 t = __floats2bfloat162_rn(a, b);
    return *reinterpret_cast<uint32_t*>(&t);
}
// split two fp32 into packed bf16 hi pair + bf16 residual pair
__device__ __forceinline__ void split2(float p0, float p1,
                                       uint32_t& hi, uint32_t& lo) {
    const uint32_t h = packbf(p0, p1);
    const float h0 = __uint_as_float(h << 16);
    const float h1 = __uint_as_float(h & 0xFFFF0000u);
    lo = packbf(p0 - h0, p1 - h1);
    hi = h;
}

// ---------------------------------------------------------------------------
// One fused hi/lo split over hs + Wq + Wk + Wv + Wo; 4 float4 per thread (MLP)
// ---------------------------------------------------------------------------
#define N4_HS (S_LEN * HID / 4)
#define N4_WQ (HID * HID / 4)
#define N4_WK (DKV * HID / 4)
#define SEG1 (N4_HS)
#define SEG2 (SEG1 + N4_WQ)
#define SEG3 (SEG2 + N4_WK)
#define SEG4 (SEG3 + N4_WK)
#define SEG5 (SEG4 + N4_WQ)

__global__ __launch_bounds__(256) void split5(
    const float* __restrict__ hs, const float* __restrict__ wq,
    const float* __restrict__ wk, const float* __restrict__ wv,
    const float* __restrict__ wo,
    __nv_bfloat16* __restrict__ hsh, __nv_bfloat16* __restrict__ hsl,
    __nv_bfloat16* __restrict__ wqh, __nv_bfloat16* __restrict__ wql,
    __nv_bfloat16* __restrict__ wkh, __nv_bfloat16* __restrict__ wkl,
    __nv_bfloat16* __restrict__ wvh, __nv_bfloat16* __restrict__ wvl,
    __nv_bfloat16* __restrict__ woh, __nv_bfloat16* __restrict__ wol)
{
    const int base = (blockIdx.x * blockDim.x + threadIdx.x) * 4;
    float4 v[4];
    __nv_bfloat16 *hp[4], *lp[4];
    int off[4];
    bool ok[4];
#pragma unroll
    for (int j = 0; j < 4; j++) {
        const int idx = base + j;
        ok[j] = (idx < SEG5);
        const float* x;
        __nv_bfloat16 *h, *l;
        int o;
        if (idx < SEG1)      { x = hs; h = hsh; l = hsl; o = idx; }
        else if (idx < SEG2) { x = wq; h = wqh; l = wql; o = idx - SEG1; }
        else if (idx < SEG3) { x = wk; h = wkh; l = wkl; o = idx - SEG2; }
        else if (idx < SEG4) { x = wv; h = wvh; l = wvl; o = idx - SEG3; }
        else                 { x = wo; h = woh; l = wol; o = idx - SEG4; }
        if (ok[j]) v[j] = ((const float4*)x)[o];
        hp[j] = h; lp[j] = l; off[j] = o;
    }
#pragma unroll
    for (int j = 0; j < 4; j++) {
        if (!ok[j]) continue;
        uint32_t h01, l01, h23, l23;
        split2(v[j].x, v[j].y, h01, l01);
        split2(v[j].z, v[j].w, h23, l23);
        uint32_t* hq = (uint32_t*)(hp[j] + off[j] * 4);
        uint32_t* lq = (uint32_t*)(lp[j] + off[j] * 4);
        hq[0] = h01; hq[1] = h23;
        lq[0] = l01; lq[1] = l23;
    }
}

// ---------------------------------------------------------------------------
// Shared GEMM tile config
// ---------------------------------------------------------------------------
#define TPITCH 80
#define TILE_B 10240
#define STAGE_B 40960
#define GEMM_SMEM_BYTES (2 * STAGE_B)
#define CPITCH 132

// ---------------------------------------------------------------------------
// Fused QKV GEMM (bf16x3) + fused RoPE. Grid (36, 16).
// bng<3584: Q (rope->hi/lo); <4096: K (rope->hi/lo); else V (direct hi/lo).
// ---------------------------------------------------------------------------
__global__ __launch_bounds__(256, 2) void gemm_qkv(
    const __nv_bfloat16* __restrict__ Ah, const __nv_bfloat16* __restrict__ Al,
    const __nv_bfloat16* __restrict__ WqH, const __nv_bfloat16* __restrict__ WqL,
    const __nv_bfloat16* __restrict__ WkH, const __nv_bfloat16* __restrict__ WkL,
    const __nv_bfloat16* __restrict__ WvH, const __nv_bfloat16* __restrict__ WvL,
    const float* __restrict__ bq, const float* __restrict__ bk,
    const float* __restrict__ bv,
    const float* __restrict__ cosb, const float* __restrict__ sinb,
    __nv_bfloat16* __restrict__ qh, __nv_bfloat16* __restrict__ ql,
    __nv_bfloat16* __restrict__ kh, __nv_bfloat16* __restrict__ kl,
    __nv_bfloat16* __restrict__ vhO, __nv_bfloat16* __restrict__ vlO)
{
    extern __shared__ __align__(128) char smem[];
    const uint32_t sb = smem_u32(smem);
    const int tid  = threadIdx.x;
    const int wid  = tid >> 5;
    const int lane = tid & 31;
    const int warp_m = wid & 3;
    const int warp_n = wid >> 2;
    const int bm  = blockIdx.y * 128;
    const int bng = blockIdx.x * 128;
    const int nk  = HID >> 5;

    const __nv_bfloat16 *Bh, *Bl;
    const float* bias;
    if (bng < HID) {
        Bh = WqH + (size_t)bng * HID; Bl = WqL + (size_t)bng * HID; bias = bq + bng;
    } else if (bng < HID + DKV) {
        const int o = bng - HID;
        Bh = WkH + (size_t)o * HID; Bl = WkL + (size_t)o * HID; bias = bk + o;
    } else {
        const int o = bng - HID - DKV;
        Bh = WvH + (size_t)o * HID; Bl = WvL + (size_t)o * HID; bias = bv + o;
    }

    const __nv_bfloat16* base[4] = {Ah + (size_t)bm * HID, Al + (size_t)bm * HID,
                                    Bh, Bl};

    auto load_stage = [&](int s, int kb) {
#pragma unroll
        for (int i = 0; i < 8; ++i) {
            const int c    = (i << 8) + tid;
            const int tile = c >> 9;
            const int rem  = c & 511;
            const int r    = rem >> 2;
            const int j    = rem & 3;
            const __nv_bfloat16* g = base[tile] + (size_t)r * HID + kb + (j << 3);
            cp_async16(sb + s * STAGE_B + tile * TILE_B + r * TPITCH + (j << 4), g);
        }
    };

    float acc[2][8][4];
#pragma unroll
    for (int mt = 0; mt < 2; mt++)
#pragma unroll
        for (int nt = 0; nt < 8; nt++)
#pragma unroll
            for (int e = 0; e < 4; e++) acc[mt][nt][e] = 0.0f;

    load_stage(0, 0);
    cp_commit();

    const uint32_t a_off = (uint32_t)(warp_m * 32 + (lane & 15)) * TPITCH
                         + ((lane >> 4) << 4);
    const uint32_t b_n   = (uint32_t)(warp_n * 64 + ((lane >> 4) << 3) + (lane & 7));
    const uint32_t b_off = b_n * TPITCH + (((lane >> 3) & 1) << 4);

    for (int i = 0; i < nk; ++i) {
        const int s = i & 1;
        if (i + 1 < nk) {
            load_stage(s ^ 1, (i + 1) << 5);
            cp_commit();
            asm volatile("cp.async.wait_group 1;" ::: "memory");
        } else {
            asm volatile("cp.async.wait_group 0;" ::: "memory");
        }
        __syncthreads();

        const uint32_t st = sb + s * STAGE_B;
#pragma unroll
        for (int k16 = 0; k16 < 2; k16++) {
            const uint32_t kb16 = k16 << 5;
            uint32_t a[2][2][4];
            ldsm4(a[0][0], st + 0 * TILE_B + a_off + kb16);
            ldsm4(a[0][1], st + 0 * TILE_B + a_off + kb16 + 16 * TPITCH);
            ldsm4(a[1][0], st + 1 * TILE_B + a_off + kb16);
            ldsm4(a[1][1], st + 1 * TILE_B + a_off + kb16 + 16 * TPITCH);

            uint32_t b[4][4];
#pragma unroll
            for (int q = 0; q < 4; q++)
                ldsm4(b[q], st + 2 * TILE_B + b_off + kb16 + (uint32_t)q * 16 * TPITCH);
#pragma unroll
            for (int mt = 0; mt < 2; mt++)
#pragma unroll
                for (int nt = 0; nt < 8; nt++) {
                    mma16816(acc[mt][nt], a[0][mt], &b[nt >> 1][(nt & 1) * 2]);
                    mma16816(acc[mt][nt], a[1][mt], &b[nt >> 1][(nt & 1) * 2]);
                }
#pragma unroll
            for (int q = 0; q < 4; q++)
                ldsm4(b[q], st + 3 * TILE_B + b_off + kb16 + (uint32_t)q * 16 * TPITCH);
#pragma unroll
            for (int mt = 0; mt < 2; mt++)
#pragma unroll
                for (int nt = 0; nt < 8; nt++)
                    mma16816(acc[mt][nt], a[0][mt], &b[nt >> 1][(nt & 1) * 2]);
        }
        __syncthreads();
    }

    const int g  = lane >> 2;
    const int ti = lane & 3;

    if (bng >= HID + DKV) {
        // ---- V epilogue: direct bf16 hi/lo ----
        const int o = bng - HID - DKV;
        __nv_bfloat16* Oh = vhO + o;
        __nv_bfloat16* Ol = vlO + o;
#pragma unroll
        for (int mt = 0; mt < 2; mt++) {
            const int row0 = bm + warp_m * 32 + mt * 16 + g;
#pragma unroll
            for (int nt = 0; nt < 8; nt++) {
                const int col = warp_n * 64 + nt * 8 + ti * 2;
                const float b0 = bias[col], b1 = bias[col + 1];
                uint32_t h0, l0, h1, l1;
                split2(acc[mt][nt][0] + b0, acc[mt][nt][1] + b1, h0, l0);
                split2(acc[mt][nt][2] + b0, acc[mt][nt][3] + b1, h1, l1);
                *(uint32_t*)(Oh + (size_t)row0 * DKV + col)       = h0;
                *(uint32_t*)(Oh + (size_t)(row0 + 8) * DKV + col) = h1;
                *(uint32_t*)(Ol + (size_t)row0 * DKV + col)       = l0;
                *(uint32_t*)(Ol + (size_t)(row0 + 8) * DKV + col) = l1;
            }
        }
    } else {
        // ---- Q/K epilogue: stage to smem, apply RoPE, emit hi/lo ----
        float* cst = (float*)smem;
#pragma unroll
        for (int mt = 0; mt < 2; mt++) {
            const int r0 = warp_m * 32 + mt * 16 + g;
#pragma unroll
            for (int nt = 0; nt < 8; nt++) {
                const int col = warp_n * 64 + nt * 8 + ti * 2;
                const float b0 = bias[col], b1 = bias[col + 1];
                *(float2*)&cst[r0 * CPITCH + col] =
                    make_float2(acc[mt][nt][0] + b0, acc[mt][nt][1] + b1);
                *(float2*)&cst[(r0 + 8) * CPITCH + col] =
                    make_float2(acc[mt][nt][2] + b0, acc[mt][nt][3] + b1);
            }
        }
        __syncthreads();

        const bool isQ = (bng < HID);
        const int colbase = isQ ? bng : (bng - HID);
        const int nout = isQ ? HID : DKV;
        __nv_bfloat16* oh = isQ ? qh : kh;
        __nv_bfloat16* ol = isQ ? ql : kl;

        const int rsub = tid >> 6;          // 0..3
        const int d    = tid & 63;          // 0..63
#pragma unroll 4
        for (int it = 0; it < 32; ++it) {
            const int r  = it * 4 + rsub;
            const int sg = bm + r;
            const float x1 = cst[r * CPITCH + d];
            const float x2 = cst[r * CPITCH + 64 + d];
            const float c1 = cosb[(size_t)sg * DH + d];
            const float c2 = cosb[(size_t)sg * DH + 64 + d];
            const float s1 = sinb[(size_t)sg * DH + d];
            const float s2 = sinb[(size_t)sg * DH + 64 + d];
            const float y1 = x1 * c1 - x2 * s1;
            const float y2 = x2 * c2 + x1 * s2;
            const __nv_bfloat16 h1 = __float2bfloat16(y1);
            const __nv_bfloat16 h2 = __float2bfloat16(y2);
            const size_t ob = (size_t)sg * nout + colbase + d;
            oh[ob]      = h1;
            oh[ob + 64] = h2;
            ol[ob]      = __float2bfloat16(y1 - __bfloat162float(h1));
            ol[ob + 64] = __float2bfloat16(y2 - __bfloat162float(h2));
        }
    }
}

// ---------------------------------------------------------------------------
// Split-K(2) bf16x3 GEMM for O projection. Grid (28, 16, 2).
// z=0 writes Cp0, z=1 writes Cp1; host adds them after.
// ---------------------------------------------------------------------------
__global__ __launch_bounds__(256, 2) void gemm_osplit(
    const __nv_bfloat16* __restrict__ Ah, const __nv_bfloat16* __restrict__ Al,
    const __nv_bfloat16* __restrict__ Bh, const __nv_bfloat16* __restrict__ Bl,
    float* __restrict__ Cp0, float* __restrict__ Cp1)
{
    extern __shared__ __align__(128) char smem[];
    const uint32_t sb = smem_u32(smem);
    const int tid  = threadIdx.x;
    const int wid  = tid >> 5;
    const int lane = tid & 31;
    const int warp_m = wid & 3;
    const int warp_n = wid >> 2;
    const int bm = blockIdx.y * 128;
    const int bn = blockIdx.x * 128;
    const int kz = blockIdx.z * (HID / 2);
    const int nk = (HID / 2) >> 5;   // 56
    float* Cw = blockIdx.z ? Cp1 : Cp0;

    const __nv_bfloat16* base[4] = {Ah + (size_t)bm * HID + kz,
                                    Al + (size_t)bm * HID + kz,
                                    Bh + (size_t)bn * HID + kz,
                                    Bl + (size_t)bn * HID + kz};

    auto load_stage = [&](int s, int kb) {
#pragma unroll
        for (int i = 0; i < 8; ++i) {
            const int c    = (i << 8) + tid;
            const int tile = c >> 9;
            const int rem  = c & 511;
            const int r    = rem >> 2;
            const int j    = rem & 3;
            const __nv_bfloat16* g = base[tile] + (size_t)r * HID + kb + (j << 3);
            cp_async16(sb + s * STAGE_B + tile * TILE_B + r * TPITCH + (j << 4), g);
        }
    };

    float acc[2][8][4];
#pragma unroll
    for (int mt = 0; mt < 2; mt++)
#pragma unroll
        for (int nt = 0; nt < 8; nt++)
#pragma unroll
            for (int e = 0; e < 4; e++) acc[mt][nt][e] = 0.0f;

    load_stage(0, 0);
    cp_commit();

    const uint32_t a_off = (uint32_t)(warp_m * 32 + (lane & 15)) * TPITCH
                         + ((lane >> 4) << 4);
    const uint32_t b_n   = (uint32_t)(warp_n * 64 + ((lane >> 4) << 3) + (lane & 7));
    const uint32_t b_off = b_n * TPITCH + (((lane >> 3) & 1) << 4);

    for (int i = 0; i < nk; ++i) {
        const int s = i & 1;
        if (i + 1 < nk) {
            load_stage(s ^ 1, (i + 1) << 5);
            cp_commit();
            asm volatile("cp.async.wait_group 1;" ::: "memory");
        } else {
            asm volatile("cp.async.wait_group 0;" ::: "memory");
        }
        __syncthreads();

        const uint32_t st = sb + s * STAGE_B;
#pragma unroll
        for (int k16 = 0; k16 < 2; k16++) {
            const uint32_t kb16 = k16 << 5;
            uint32_t a[2][2][4];
            ldsm4(a[0][0], st + 0 * TILE_B + a_off + kb16);
            ldsm4(a[0][1], st + 0 * TILE_B + a_off + kb16 + 16 * TPITCH);
            ldsm4(a[1][0], st + 1 * TILE_B + a_off + kb16);
            ldsm4(a[1][1], st + 1 * TILE_B + a_off + kb16 + 16 * TPITCH);

            uint32_t b[4][4];
#pragma unroll
            for (int q = 0; q < 4; q++)
                ldsm4(b[q], st + 2 * TILE_B + b_off + kb16 + (uint32_t)q * 16 * TPITCH);
#pragma unroll
            for (int mt = 0; mt < 2; mt++)
#pragma unroll
                for (int nt = 0; nt < 8; nt++) {
                    mma16816(acc[mt][nt], a[0][mt], &b[nt >> 1][(nt & 1) * 2]);
                    mma16816(acc[mt][nt], a[1][mt], &b[nt >> 1][(nt & 1) * 2]);
                }
#pragma unroll
            for (int q = 0; q < 4; q++)
                ldsm4(b[q], st + 3 * TILE_B + b_off + kb16 + (uint32_t)q * 16 * TPITCH);
#pragma unroll
            for (int mt = 0; mt < 2; mt++)
#pragma unroll
                for (int nt = 0; nt < 8; nt++)
                    mma16816(acc[mt][nt], a[0][mt], &b[nt >> 1][(nt & 1) * 2]);
        }
        __syncthreads();
    }

    const int g  = lane >> 2;
    const int ti = lane & 3;
#pragma unroll
    for (int mt = 0; mt < 2; mt++) {
        const int row0 = bm + warp_m * 32 + mt * 16 + g;
#pragma unroll
        for (int nt = 0; nt < 8; nt++) {
            const int col = bn + warp_n * 64 + nt * 8 + ti * 2;
            *(float2*)(Cw + (size_t)row0 * HID + col) =
                make_float2(acc[mt][nt][0], acc[mt][nt][1]);
            *(float2*)(Cw + (size_t)(row0 + 8) * HID + col) =
                make_float2(acc[mt][nt][2], acc[mt][nt][3]);
        }
    }
}

// out += partial
__global__ __launch_bounds__(256) void add_f4(
    float* __restrict__ o, const float* __restrict__ p, int n4)
{
    int i = blockIdx.x * blockDim.x + threadIdx.x;
    if (i >= n4) return;
    float4 a = ((float4*)o)[i];
    float4 b = ((const float4*)p)[i];
    a.x += b.x; a.y += b.y; a.z += b.z; a.w += b.w;
    ((float4*)o)[i] = a;
}

// ---------------------------------------------------------------------------
// HMMA bf16x3 causal flash attention. Grid (16, 28), 256 thr.
// ---------------------------------------------------------------------------
#define APITCH 272
#define QHALF  34816
#define KVSTG  69632
#define ATTN_SMEM_BYTES (QHALF * 2 + KVSTG * 2)   // 208896

__global__ __launch_bounds__(256, 1) void attn_hmma(
    const __nv_bfloat16* __restrict__ qh_, const __nv_bfloat16* __restrict__ ql_,
    const __nv_bfloat16* __restrict__ kh_, const __nv_bfloat16* __restrict__ kl_,
    const __nv_bfloat16* __restrict__ vh_, const __nv_bfloat16* __restrict__ vl_,
    __nv_bfloat16* __restrict__ aoh, __nv_bfloat16* __restrict__ aol)
{
    extern __shared__ __align__(128) char smem[];
    const uint32_t sb = smem_u32(smem);
    const int tid  = threadIdx.x;
    const int wid  = tid >> 5;
    const int lane = tid & 31;
    const int qb = gridDim.x - 1 - blockIdx.x;     // big tiles first
    const int h  = blockIdx.y;
    const int kvh = h / N_REP;
    const int q0 = qb * 128;
    const int m0 = wid * 16;
    const int nkt = 2 * qb + 2;
    const float kscale = 0.08838834764831845f * 1.4426950408889634f;

#pragma unroll
    for (int it = 0; it < 16; ++it) {
        int idx = it * 256 + tid;
        int half = idx >> 11, rem = idx & 2047;
        int r = rem >> 4, c = rem & 15;
        const __nv_bfloat16* src =
            (half ? ql_ : qh_) + (size_t)(q0 + r) * HID + h * DH + c * 8;
        cp_async16(sb + half * QHALF + r * APITCH + c * 16, src);
    }
    cp_commit();

    auto load_kv = [&](int s, int kt) {
        const int k0 = kt * 64;
        const __nv_bfloat16* srcs[4] = {kh_, kl_, vh_, vl_};
#pragma unroll
        for (int it = 0; it < 16; ++it) {
            int idx = it * 256 + tid;
            int tz = idx >> 10, rem = idx & 1023;
            int r = rem >> 4, c = rem & 15;
            const __nv_bfloat16* src =
                srcs[tz] + (size_t)(k0 + r) * DKV + kvh * DH + c * 8;
            cp_async16(sb + 2 * QHALF + s * KVSTG + tz * 17408 + r * APITCH + c * 16,
                       src);
        }
        cp_commit();
    };
    load_kv(0, 0);

    float oacc[16][4];
#pragma unroll
    for (int f = 0; f < 16; f++)
#pragma unroll
        for (int e = 0; e < 4; e++) oacc[f][e] = 0.0f;
    float m_lo = -1e30f, m_hi = -1e30f, l_lo = 0.0f, l_hi = 0.0f;

    const uint32_t a_q   = sb + (uint32_t)(m0 + (lane & 15)) * APITCH
                         + ((lane >> 4) << 4);
    const uint32_t bkrow = ((lane >> 4) << 3) + (lane & 7);
    const uint32_t bkoff = (((lane >> 3) & 1) << 4);
    const uint32_t vrow  = (lane & 15);
    const uint32_t vcoff = ((lane >> 4) << 4);
    const int row_off  = lane >> 2;
    const int col_base = (lane & 3) * 2;
    const int row_lo_g = q0 + m0 + row_off;
    const int row_hi_g = row_lo_g + 8;

    for (int kt = 0; kt < nkt; ++kt) {
        const int s  = kt & 1;
        const int k0 = kt * 64;
        if (kt + 1 < nkt) {
            load_kv(s ^ 1, kt + 1);
            asm volatile("cp.async.wait_group 1;" ::: "memory");
        } else {
            asm volatile("cp.async.wait_group 0;" ::: "memory");
        }
        __syncthreads();

        const uint32_t kvb = sb + 2 * QHALF + s * KVSTG;
        const uint32_t khb = kvb, klb = kvb + 17408;
        const uint32_t vhb = kvb + 34816, vlb = kvb + 52224;

        float sacc[8][4];
#pragma unroll
        for (int f = 0; f < 8; f++)
#pragma unroll
            for (int e = 0; e < 4; e++) sacc[f][e] = 0.0f;

#pragma unroll
        for (int k16 = 0; k16 < 8; k16++) {
            uint32_t ah[4], al[4], bt[4];
            ldsm4(ah, a_q + k16 * 32);
            ldsm4(al, a_q + QHALF + k16 * 32);
#pragma unroll
            for (int g = 0; g < 4; g++) {
                const uint32_t baddr =
                    (uint32_t)(16 * g + bkrow) * APITCH + bkoff + k16 * 32;
                ldsm4(bt, khb + baddr);
                mma16816(sacc[2 * g],     ah, bt);
                mma16816(sacc[2 * g + 1], ah, bt + 2);
                mma16816(sacc[2 * g],     al, bt);
                mma16816(sacc[2 * g + 1], al, bt + 2);
                ldsm4(bt, klb + baddr);
                mma16816(sacc[2 * g],     ah, bt);
                mma16816(sacc[2 * g + 1], ah, bt + 2);
            }
        }

        const bool flag = (k0 + 63 > q0);
        float tmx_lo = -1e30f, tmx_hi = -1e30f;
#pragma unroll
        for (int f = 0; f < 8; f++) {
            const int c0g = k0 + 8 * f + col_base;
#pragma unroll
            for (int j = 0; j < 2; j++) {
                float x = sacc[f][j] * kscale;
                if (flag && (c0g + j > row_lo_g)) x = -1e30f;
                sacc[f][j] = x;
                tmx_lo = fmaxf(tmx_lo, x);
                float y = sacc[f][j + 2] * kscale;
                if (flag && (c0g + j > row_hi_g)) y = -1e30f;
                sacc[f][j + 2] = y;
                tmx_hi = fmaxf(tmx_hi, y);
            }
        }
        tmx_lo = fmaxf(tmx_lo, __shfl_xor_sync(0xffffffffu, tmx_lo, 1));
        tmx_lo = fmaxf(tmx_lo, __shfl_xor_sync(0xffffffffu, tmx_lo, 2));
        tmx_hi = fmaxf(tmx_hi, __shfl_xor_sync(0xffffffffu, tmx_hi, 1));
        tmx_hi = fmaxf(tmx_hi, __shfl_xor_sync(0xffffffffu, tmx_hi, 2));

        const float mn_lo = fmaxf(m_lo, tmx_lo);
        const float mn_hi = fmaxf(m_hi, tmx_hi);
        const float al_lo = ex2f(m_lo - mn_lo);
        const float al_hi = ex2f(m_hi - mn_hi);
        m_lo = mn_lo; m_hi = mn_hi;

        uint32_t Ph[16], Pl[16];
        float ps_lo = 0.0f, ps_hi = 0.0f;
#pragma unroll
        for (int f = 0; f < 8; f++) {
            float p0 = ex2f(sacc[f][0] - m_lo);
            float p1 = ex2f(sacc[f][1] - m_lo);
            float p2 = ex2f(sacc[f][2] - m_hi);
            float p3 = ex2f(sacc[f][3] - m_hi);
            ps_lo += p0 + p1; ps_hi += p2 + p3;
            const int c  = f >> 1;
            const int rb = (f & 1) * 2;
            split2(p0, p1, Ph[c * 4 + rb],     Pl[c * 4 + rb]);
            split2(p2, p3, Ph[c * 4 + rb + 1], Pl[c * 4 + rb + 1]);
        }
        ps_lo += __shfl_xor_sync(0xffffffffu, ps_lo, 1);
        ps_lo += __shfl_xor_sync(0xffffffffu, ps_lo, 2);
        ps_hi += __shfl_xor_sync(0xffffffffu, ps_hi, 1);
        ps_hi += __shfl_xor_sync(0xffffffffu, ps_hi, 2);
        l_lo = l_lo * al_lo + ps_lo;
        l_hi = l_hi * al_hi + ps_hi;

#pragma unroll
        for (int f = 0; f < 16; f++) {
            oacc[f][0] *= al_lo; oacc[f][1] *= al_lo;
            oacc[f][2] *= al_hi; oacc[f][3] *= al_hi;
        }

#pragma unroll
        for (int c = 0; c < 4; c++) {
#pragma unroll
            for (int g = 0; g < 8; g++) {
                const uint32_t baddr =
                    (uint32_t)(16 * c + vrow) * APITCH + 32 * g + vcoff;
                uint32_t bt[4];
                ldsm4t(bt, vhb + baddr);
                mma16816(oacc[2 * g],     &Ph[c * 4], bt);
                mma16816(oacc[2 * g + 1], &Ph[c * 4], bt + 2);
                mma16816(oacc[2 * g],     &Pl[c * 4], bt);
                mma16816(oacc[2 * g + 1], &Pl[c * 4], bt + 2);
                ldsm4t(bt, vlb + baddr);
                mma16816(oacc[2 * g],     &Ph[c * 4], bt);
                mma16816(oacc[2 * g + 1], &Ph[c * 4], bt + 2);
            }
        }
        __syncthreads();
    }

    // ---- normalize + direct hi/lo bf16 store ----
    const float inv_lo = 1.0f / l_lo;
    const float inv_hi = 1.0f / l_hi;
#pragma unroll
    for (int f = 0; f < 16; f++) {
        const int col = 8 * f + col_base;
        const size_t off_lo = (size_t)row_lo_g * HID + h * DH + col;
        const size_t off_hi = (size_t)row_hi_g * HID + h * DH + col;
        uint32_t h0, l0, h1, l1;
        split2(oacc[f][0] * inv_lo, oacc[f][1] * inv_lo, h0, l0);
        split2(oacc[f][2] * inv_hi, oacc[f][3] * inv_hi, h1, l1);
        *(uint32_t*)(aoh + off_lo) = h0;
        *(uint32_t*)(aoh + off_hi) = h1;
        *(uint32_t*)(aol + off_lo) = l0;
        *(uint32_t*)(aol + off_hi) = l1;
    }
}

// ---------------------------------------------------------------------------
// Launch
// ---------------------------------------------------------------------------
extern "C" void kernel_launch(void* const* d_in, const int* in_sizes, int n_in,
                              void* d_out, int out_size)
{
    const float* hs   = (const float*)d_in[0];
    const float* Wq   = (const float*)d_in[1];
    const float* bq   = (const float*)d_in[2];
    const float* Wk   = (const float*)d_in[3];
    const float* bk   = (const float*)d_in[4];
    const float* Wv   = (const float*)d_in[5];
    const float* bv   = (const float*)d_in[6];
    const float* Wo   = (const float*)d_in[7];
    const float* cosb = (const float*)d_in[8];
    const float* sinb = (const float*)d_in[9];
    float* out = (float*)d_out;

    float* P1;
    cudaGetSymbolAddress((void**)&P1, g_P1);

    __nv_bfloat16 *hsh, *hsl, *aoh, *aol, *wqh, *wql, *wkh, *wkl, *wvh, *wvl, *woh, *wol;
    __nv_bfloat16 *qh, *ql, *kh, *kl, *vh, *vl;
    cudaGetSymbolAddress((void**)&hsh, g_hs_h); cudaGetSymbolAddress((void**)&hsl, g_hs_l);
    cudaGetSymbolAddress((void**)&aoh, g_ao_h); cudaGetSymbolAddress((void**)&aol, g_ao_l);
    cudaGetSymbolAddress((void**)&wqh, g_wq_h); cudaGetSymbolAddress((void**)&wql, g_wq_l);
    cudaGetSymbolAddress((void**)&wkh, g_wk_h); cudaGetSymbolAddress((void**)&wkl, g_wk_l);
    cudaGetSymbolAddress((void**)&wvh, g_wv_h); cudaGetSymbolAddress((void**)&wvl, g_wv_l);
    cudaGetSymbolAddress((void**)&woh, g_wo_h); cudaGetSymbolAddress((void**)&wol, g_wo_l);
    cudaGetSymbolAddress((void**)&qh, g_q_h);   cudaGetSymbolAddress((void**)&ql, g_q_l);
    cudaGetSymbolAddress((void**)&kh, g_k_h);   cudaGetSymbolAddress((void**)&kl, g_k_l);
    cudaGetSymbolAddress((void**)&vh, g_v_h);   cudaGetSymbolAddress((void**)&vl, g_v_l);

    cudaFuncSetAttribute(gemm_qkv, cudaFuncAttributeMaxDynamicSharedMemorySize,
                         GEMM_SMEM_BYTES);
    cudaFuncSetAttribute(gemm_osplit, cudaFuncAttributeMaxDynamicSharedMemorySize,
                         GEMM_SMEM_BYTES);
    cudaFuncSetAttribute(attn_hmma, cudaFuncAttributeMaxDynamicSharedMemorySize,
                         ATTN_SMEM_BYTES);

    // single fused hi/lo split for hs + all weights (4 float4 / thread)
    split5<<<(SEG5 / 4 + 255) / 256, 256>>>(hs, Wq, Wk, Wv, Wo,
                                            hsh, hsl, wqh, wql, wkh, wkl,
                                            wvh, wvl, woh, wol);

    // fused QKV projection + RoPE: emits q/k/v hi-lo bf16 directly
    gemm_qkv<<<dim3((HID + 2 * DKV) / 128, S_LEN / 128), 256, GEMM_SMEM_BYTES>>>(
        hsh, hsl, wqh, wql, wkh, wkl, wvh, wvl, bq, bk, bv,
        cosb, sinb, qh, ql, kh, kl, vh, vl);

    attn_hmma<<<dim3(S_LEN / 128, NHQ), 256, ATTN_SMEM_BYTES>>>(
        qh, ql, kh, kl, vh, vl, aoh, aol);

    // split-K(2) O projection + reduction
    gemm_osplit<<<dim3(HID / 128, S_LEN / 128, 2), 256, GEMM_SMEM_BYTES>>>(
        aoh, aol, woh, wol, out, P1);
    add_f4<<<(S_LEN * HID / 4 + 255) / 256, 256>>>(out, P1, S_LEN * HID / 4);
}

// round 14
// speedup vs baseline: 1.0787x; 1.0787x over previous
#include <cuda_runtime.h>
#include <cuda_bf16.h>
#include <stdint.h>
#include <math.h>

#define S_LEN 2048
#define HID   3584
#define NHQ   28
#define NKV   4
#define DH    128
#define DKV   (NKV * DH)   // 512
#define N_REP (NHQ / NKV)  // 7

// ---------------- scratch (__device__ globals; no allocs allowed) ----------
__device__ float g_P1[S_LEN * HID];    // split-K partial for O projection

__device__ __nv_bfloat16 g_hs_h[S_LEN * HID],  g_hs_l[S_LEN * HID];
__device__ __nv_bfloat16 g_ao_h[S_LEN * HID],  g_ao_l[S_LEN * HID];
__device__ __nv_bfloat16 g_wq_h[HID * HID],    g_wq_l[HID * HID];
__device__ __nv_bfloat16 g_wo_h[HID * HID],    g_wo_l[HID * HID];
__device__ __nv_bfloat16 g_wk_h[DKV * HID],    g_wk_l[DKV * HID];
__device__ __nv_bfloat16 g_wv_h[DKV * HID],    g_wv_l[DKV * HID];

// post-RoPE bf16 splits for attention
__device__ __nv_bfloat16 g_q_h[S_LEN * HID],  g_q_l[S_LEN * HID];
__device__ __nv_bfloat16 g_k_h[S_LEN * DKV],  g_k_l[S_LEN * DKV];
__device__ __nv_bfloat16 g_v_h[S_LEN * DKV],  g_v_l[S_LEN * DKV];

// ---------------- PTX helpers ---------------------------------------------
__device__ __forceinline__ uint32_t smem_u32(const void* p) {
    uint32_t a;
    asm("{ .reg .u64 t; cvta.to.shared.u64 t, %1; cvt.u32.u64 %0, t; }"
        : "=r"(a) : "l"(p));
    return a;
}
__device__ __forceinline__ void cp_async16(uint32_t dst, const void* src) {
    asm volatile("cp.async.cg.shared.global [%0], [%1], 16;\n"
                 :: "r"(dst), "l"(src) : "memory");
}
__device__ __forceinline__ void cp_commit() {
    asm volatile("cp.async.commit_group;" ::: "memory");
}
__device__ __forceinline__ void ldsm4(uint32_t* r, uint32_t addr) {
    asm volatile("ldmatrix.sync.aligned.m8n8.x4.shared.b16 {%0,%1,%2,%3}, [%4];\n"
                 : "=r"(r[0]), "=r"(r[1]), "=r"(r[2]), "=r"(r[3]) : "r"(addr));
}
__device__ __forceinline__ void ldsm4t(uint32_t* r, uint32_t addr) {
    asm volatile("ldmatrix.sync.aligned.m8n8.x4.trans.shared.b16 {%0,%1,%2,%3}, [%4];\n"
                 : "=r"(r[0]), "=r"(r[1]), "=r"(r[2]), "=r"(r[3]) : "r"(addr));
}
__device__ __forceinline__ void mma16816(float* c, const uint32_t* a,
                                         const uint32_t* b) {
    asm volatile(
        "mma.sync.aligned.m16n8k16.row.col.f32.bf16.bf16.f32 "
        "{%0,%1,%2,%3}, {%4,%5,%6,%7}, {%8,%9}, {%0,%1,%2,%3};\n"
        : "+f"(c[0]), "+f"(c[1]), "+f"(c[2]), "+f"(c[3])
        : "r"(a[0]), "r"(a[1]), "r"(a[2]), "r"(a[3]), "r"(b[0]), "r"(b[1]));
}
__device__ __forceinline__ float ex2f(float x) {
    float y;
    asm("ex2.approx.ftz.f32 %0, %1;" : "=f"(y) : "f"(x));
    return y;
}
__device__ __forceinline__ uint32_t packbf(float a, float b) {
    __nv_bfloat162 t = __floats2bfloat162_rn(a, b);
    return *reinterpret_cast<uint32_t*>(&t);
}
// split two fp32 into packed bf16 hi pair + bf16 residual pair
__device__ __forceinline__ void split2(float p0, float p1,
                                       uint32_t& hi, uint32_t& lo) {
    const uint32_t h = packbf(p0, p1);
    const float h0 = __uint_as_float(h << 16);
    const float h1 = __uint_as_float(h & 0xFFFF0000u);
    lo = packbf(p0 - h0, p1 - h1);
    hi = h;
}

// ---------------------------------------------------------------------------
// One fused hi/lo split over hs + Wq + Wk + Wv + Wo.
// Grid-strided x4: each batch coalesced, 4 independent loads in flight.
// ---------------------------------------------------------------------------
#define N4_HS (S_LEN * HID / 4)
#define N4_WQ (HID * HID / 4)
#define N4_WK (DKV * HID / 4)
#define SEG1 (N4_HS)
#define SEG2 (SEG1 + N4_WQ)
#define SEG3 (SEG2 + N4_WK)
#define SEG4 (SEG3 + N4_WK)
#define SEG5 (SEG4 + N4_WQ)

__global__ __launch_bounds__(256) void split5(
    const float* __restrict__ hs, const float* __restrict__ wq,
    const float* __restrict__ wk, const float* __restrict__ wv,
    const float* __restrict__ wo,
    __nv_bfloat16* __restrict__ hsh, __nv_bfloat16* __restrict__ hsl,
    __nv_bfloat16* __restrict__ wqh, __nv_bfloat16* __restrict__ wql,
    __nv_bfloat16* __restrict__ wkh, __nv_bfloat16* __restrict__ wkl,
    __nv_bfloat16* __restrict__ wvh, __nv_bfloat16* __restrict__ wvl,
    __nv_bfloat16* __restrict__ woh, __nv_bfloat16* __restrict__ wol)
{
    const int gtid   = blockIdx.x * blockDim.x + threadIdx.x;
    const int stride = gridDim.x * blockDim.x;

    float4 v[4];
    __nv_bfloat16 *hp[4], *lp[4];
    int off[4];
    bool ok[4];
#pragma unroll
    for (int t = 0; t < 4; t++) {
        const int idx = gtid + t * stride;
        ok[t] = (idx < SEG5);
        const float* x;
        __nv_bfloat16 *h, *l;
        int o;
        if (idx < SEG1)      { x = hs; h = hsh; l = hsl; o = idx; }
        else if (idx < SEG2) { x = wq; h = wqh; l = wql; o = idx - SEG1; }
        else if (idx < SEG3) { x = wk; h = wkh; l = wkl; o = idx - SEG2; }
        else if (idx < SEG4) { x = wv; h = wvh; l = wvl; o = idx - SEG3; }
        else                 { x = wo; h = woh; l = wol; o = idx - SEG4; }
        if (ok[t]) v[t] = ((const float4*)x)[o];
        hp[t] = h; lp[t] = l; off[t] = o;
    }
#pragma unroll
    for (int t = 0; t < 4; t++) {
        if (!ok[t]) continue;
        uint32_t h01, l01, h23, l23;
        split2(v[t].x, v[t].y, h01, l01);
        split2(v[t].z, v[t].w, h23, l23);
        uint32_t* hq = (uint32_t*)(hp[t] + off[t] * 4);
        uint32_t* lq = (uint32_t*)(lp[t] + off[t] * 4);
        hq[0] = h01; hq[1] = h23;
        lq[0] = l01; lq[1] = l23;
    }
}

// ---------------------------------------------------------------------------
// Shared GEMM tile config
// ---------------------------------------------------------------------------
#define TPITCH 80
#define TILE_B 10240
#define STAGE_B 40960
#define GEMM_SMEM_BYTES (2 * STAGE_B)
#define CPITCH 132

// ---------------------------------------------------------------------------
// Fused QKV GEMM (bf16x3) + fused RoPE. Grid (36, 16).
// bng<3584: Q (rope->hi/lo); <4096: K (rope->hi/lo); else V (direct hi/lo).
// ---------------------------------------------------------------------------
__global__ __launch_bounds__(256, 2) void gemm_qkv(
    const __nv_bfloat16* __restrict__ Ah, const __nv_bfloat16* __restrict__ Al,
    const __nv_bfloat16* __restrict__ WqH, const __nv_bfloat16* __restrict__ WqL,
    const __nv_bfloat16* __restrict__ WkH, const __nv_bfloat16* __restrict__ WkL,
    const __nv_bfloat16* __restrict__ WvH, const __nv_bfloat16* __restrict__ WvL,
    const float* __restrict__ bq, const float* __restrict__ bk,
    const float* __restrict__ bv,
    const float* __restrict__ cosb, const float* __restrict__ sinb,
    __nv_bfloat16* __restrict__ qh, __nv_bfloat16* __restrict__ ql,
    __nv_bfloat16* __restrict__ kh, __nv_bfloat16* __restrict__ kl,
    __nv_bfloat16* __restrict__ vhO, __nv_bfloat16* __restrict__ vlO)
{
    extern __shared__ __align__(128) char smem[];
    const uint32_t sb = smem_u32(smem);
    const int tid  = threadIdx.x;
    const int wid  = tid >> 5;
    const int lane = tid & 31;
    const int warp_m = wid & 3;
    const int warp_n = wid >> 2;
    const int bm  = blockIdx.y * 128;
    const int bng = blockIdx.x * 128;
    const int nk  = HID >> 5;

    const __nv_bfloat16 *Bh, *Bl;
    const float* bias;
    if (bng < HID) {
        Bh = WqH + (size_t)bng * HID; Bl = WqL + (size_t)bng * HID; bias = bq + bng;
    } else if (bng < HID + DKV) {
        const int o = bng - HID;
        Bh = WkH + (size_t)o * HID; Bl = WkL + (size_t)o * HID; bias = bk + o;
    } else {
        const int o = bng - HID - DKV;
        Bh = WvH + (size_t)o * HID; Bl = WvL + (size_t)o * HID; bias = bv + o;
    }

    const __nv_bfloat16* base[4] = {Ah + (size_t)bm * HID, Al + (size_t)bm * HID,
                                    Bh, Bl};

    auto load_stage = [&](int s, int kb) {
#pragma unroll
        for (int i = 0; i < 8; ++i) {
            const int c    = (i << 8) + tid;
            const int tile = c >> 9;
            const int rem  = c & 511;
            const int r    = rem >> 2;
            const int j    = rem & 3;
            const __nv_bfloat16* g = base[tile] + (size_t)r * HID + kb + (j << 3);
            cp_async16(sb + s * STAGE_B + tile * TILE_B + r * TPITCH + (j << 4), g);
        }
    };

    float acc[2][8][4];
#pragma unroll
    for (int mt = 0; mt < 2; mt++)
#pragma unroll
        for (int nt = 0; nt < 8; nt++)
#pragma unroll
            for (int e = 0; e < 4; e++) acc[mt][nt][e] = 0.0f;

    load_stage(0, 0);
    cp_commit();

    const uint32_t a_off = (uint32_t)(warp_m * 32 + (lane & 15)) * TPITCH
                         + ((lane >> 4) << 4);
    const uint32_t b_n   = (uint32_t)(warp_n * 64 + ((lane >> 4) << 3) + (lane & 7));
    const uint32_t b_off = b_n * TPITCH + (((lane >> 3) & 1) << 4);

    for (int i = 0; i < nk; ++i) {
        const int s = i & 1;
        if (i + 1 < nk) {
            load_stage(s ^ 1, (i + 1) << 5);
            cp_commit();
            asm volatile("cp.async.wait_group 1;" ::: "memory");
        } else {
            asm volatile("cp.async.wait_group 0;" ::: "memory");
        }
        __syncthreads();

        const uint32_t st = sb + s * STAGE_B;
#pragma unroll
        for (int k16 = 0; k16 < 2; k16++) {
            const uint32_t kb16 = k16 << 5;
            uint32_t a[2][2][4];
            ldsm4(a[0][0], st + 0 * TILE_B + a_off + kb16);
            ldsm4(a[0][1], st + 0 * TILE_B + a_off + kb16 + 16 * TPITCH);
            ldsm4(a[1][0], st + 1 * TILE_B + a_off + kb16);
            ldsm4(a[1][1], st + 1 * TILE_B + a_off + kb16 + 16 * TPITCH);

            uint32_t b[4][4];
#pragma unroll
            for (int q = 0; q < 4; q++)
                ldsm4(b[q], st + 2 * TILE_B + b_off + kb16 + (uint32_t)q * 16 * TPITCH);
#pragma unroll
            for (int mt = 0; mt < 2; mt++)
#pragma unroll
                for (int nt = 0; nt < 8; nt++) {
                    mma16816(acc[mt][nt], a[0][mt], &b[nt >> 1][(nt & 1) * 2]);
                    mma16816(acc[mt][nt], a[1][mt], &b[nt >> 1][(nt & 1) * 2]);
                }
#pragma unroll
            for (int q = 0; q < 4; q++)
                ldsm4(b[q], st + 3 * TILE_B + b_off + kb16 + (uint32_t)q * 16 * TPITCH);
#pragma unroll
            for (int mt = 0; mt < 2; mt++)
#pragma unroll
                for (int nt = 0; nt < 8; nt++)
                    mma16816(acc[mt][nt], a[0][mt], &b[nt >> 1][(nt & 1) * 2]);
        }
        __syncthreads();
    }

    const int g  = lane >> 2;
    const int ti = lane & 3;

    if (bng >= HID + DKV) {
        // ---- V epilogue: direct bf16 hi/lo ----
        const int o = bng - HID - DKV;
        __nv_bfloat16* Oh = vhO + o;
        __nv_bfloat16* Ol = vlO + o;
#pragma unroll
        for (int mt = 0; mt < 2; mt++) {
            const int row0 = bm + warp_m * 32 + mt * 16 + g;
#pragma unroll
            for (int nt = 0; nt < 8; nt++) {
                const int col = warp_n * 64 + nt * 8 + ti * 2;
                const float b0 = bias[col], b1 = bias[col + 1];
                uint32_t h0, l0, h1, l1;
                split2(acc[mt][nt][0] + b0, acc[mt][nt][1] + b1, h0, l0);
                split2(acc[mt][nt][2] + b0, acc[mt][nt][3] + b1, h1, l1);
                *(uint32_t*)(Oh + (size_t)row0 * DKV + col)       = h0;
                *(uint32_t*)(Oh + (size_t)(row0 + 8) * DKV + col) = h1;
                *(uint32_t*)(Ol + (size_t)row0 * DKV + col)       = l0;
                *(uint32_t*)(Ol + (size_t)(row0 + 8) * DKV + col) = l1;
            }
        }
    } else {
        // ---- Q/K epilogue: stage to smem, apply RoPE, emit hi/lo ----
        float* cst = (float*)smem;
#pragma unroll
        for (int mt = 0; mt < 2; mt++) {
            const int r0 = warp_m * 32 + mt * 16 + g;
#pragma unroll
            for (int nt = 0; nt < 8; nt++) {
                const int col = warp_n * 64 + nt * 8 + ti * 2;
                const float b0 = bias[col], b1 = bias[col + 1];
                *(float2*)&cst[r0 * CPITCH + col] =
                    make_float2(acc[mt][nt][0] + b0, acc[mt][nt][1] + b1);
                *(float2*)&cst[(r0 + 8) * CPITCH + col] =
                    make_float2(acc[mt][nt][2] + b0, acc[mt][nt][3] + b1);
            }
        }
        __syncthreads();

        const bool isQ = (bng < HID);
        const int colbase = isQ ? bng : (bng - HID);
        const int nout = isQ ? HID : DKV;
        __nv_bfloat16* oh = isQ ? qh : kh;
        __nv_bfloat16* ol = isQ ? ql : kl;

        const int rsub = tid >> 6;          // 0..3
        const int d    = tid & 63;          // 0..63
#pragma unroll 4
        for (int it = 0; it < 32; ++it) {
            const int r  = it * 4 + rsub;
            const int sg = bm + r;
            const float x1 = cst[r * CPITCH + d];
            const float x2 = cst[r * CPITCH + 64 + d];
            const float c1 = cosb[(size_t)sg * DH + d];
            const float c2 = cosb[(size_t)sg * DH + 64 + d];
            const float s1 = sinb[(size_t)sg * DH + d];
            const float s2 = sinb[(size_t)sg * DH + 64 + d];
            const float y1 = x1 * c1 - x2 * s1;
            const float y2 = x2 * c2 + x1 * s2;
            const __nv_bfloat16 h1 = __float2bfloat16(y1);
            const __nv_bfloat16 h2 = __float2bfloat16(y2);
            const size_t ob = (size_t)sg * nout + colbase + d;
            oh[ob]      = h1;
            oh[ob + 64] = h2;
            ol[ob]      = __float2bfloat16(y1 - __bfloat162float(h1));
            ol[ob + 64] = __float2bfloat16(y2 - __bfloat162float(h2));
        }
    }
}

// ---------------------------------------------------------------------------
// Split-K(2) bf16x3 GEMM for O projection. Grid (28, 16, 2).
// z=0 writes Cp0, z=1 writes Cp1; host adds them after.
// ---------------------------------------------------------------------------
__global__ __launch_bounds__(256, 2) void gemm_osplit(
    const __nv_bfloat16* __restrict__ Ah, const __nv_bfloat16* __restrict__ Al,
    const __nv_bfloat16* __restrict__ Bh, const __nv_bfloat16* __restrict__ Bl,
    float* __restrict__ Cp0, float* __restrict__ Cp1)
{
    extern __shared__ __align__(128) char smem[];
    const uint32_t sb = smem_u32(smem);
    const int tid  = threadIdx.x;
    const int wid  = tid >> 5;
    const int lane = tid & 31;
    const int warp_m = wid & 3;
    const int warp_n = wid >> 2;
    const int bm = blockIdx.y * 128;
    const int bn = blockIdx.x * 128;
    const int kz = blockIdx.z * (HID / 2);
    const int nk = (HID / 2) >> 5;   // 56
    float* Cw = blockIdx.z ? Cp1 : Cp0;

    const __nv_bfloat16* base[4] = {Ah + (size_t)bm * HID + kz,
                                    Al + (size_t)bm * HID + kz,
                                    Bh + (size_t)bn * HID + kz,
                                    Bl + (size_t)bn * HID + kz};

    auto load_stage = [&](int s, int kb) {
#pragma unroll
        for (int i = 0; i < 8; ++i) {
            const int c    = (i << 8) + tid;
            const int tile = c >> 9;
            const int rem  = c & 511;
            const int r    = rem >> 2;
            const int j    = rem & 3;
            const __nv_bfloat16* g = base[tile] + (size_t)r * HID + kb + (j << 3);
            cp_async16(sb + s * STAGE_B + tile * TILE_B + r * TPITCH + (j << 4), g);
        }
    };

    float acc[2][8][4];
#pragma unroll
    for (int mt = 0; mt < 2; mt++)
#pragma unroll
        for (int nt = 0; nt < 8; nt++)
#pragma unroll
            for (int e = 0; e < 4; e++) acc[mt][nt][e] = 0.0f;

    load_stage(0, 0);
    cp_commit();

    const uint32_t a_off = (uint32_t)(warp_m * 32 + (lane & 15)) * TPITCH
                         + ((lane >> 4) << 4);
    const uint32_t b_n   = (uint32_t)(warp_n * 64 + ((lane >> 4) << 3) + (lane & 7));
    const uint32_t b_off = b_n * TPITCH + (((lane >> 3) & 1) << 4);

    for (int i = 0; i < nk; ++i) {
        const int s = i & 1;
        if (i + 1 < nk) {
            load_stage(s ^ 1, (i + 1) << 5);
            cp_commit();
            asm volatile("cp.async.wait_group 1;" ::: "memory");
        } else {
            asm volatile("cp.async.wait_group 0;" ::: "memory");
        }
        __syncthreads();

        const uint32_t st = sb + s * STAGE_B;
#pragma unroll
        for (int k16 = 0; k16 < 2; k16++) {
            const uint32_t kb16 = k16 << 5;
            uint32_t a[2][2][4];
            ldsm4(a[0][0], st + 0 * TILE_B + a_off + kb16);
            ldsm4(a[0][1], st + 0 * TILE_B + a_off + kb16 + 16 * TPITCH);
            ldsm4(a[1][0], st + 1 * TILE_B + a_off + kb16);
            ldsm4(a[1][1], st + 1 * TILE_B + a_off + kb16 + 16 * TPITCH);

            uint32_t b[4][4];
#pragma unroll
            for (int q = 0; q < 4; q++)
                ldsm4(b[q], st + 2 * TILE_B + b_off + kb16 + (uint32_t)q * 16 * TPITCH);
#pragma unroll
            for (int mt = 0; mt < 2; mt++)
#pragma unroll
                for (int nt = 0; nt < 8; nt++) {
                    mma16816(acc[mt][nt], a[0][mt], &b[nt >> 1][(nt & 1) * 2]);
                    mma16816(acc[mt][nt], a[1][mt], &b[nt >> 1][(nt & 1) * 2]);
                }
#pragma unroll
            for (int q = 0; q < 4; q++)
                ldsm4(b[q], st + 3 * TILE_B + b_off + kb16 + (uint32_t)q * 16 * TPITCH);
#pragma unroll
            for (int mt = 0; mt < 2; mt++)
#pragma unroll
                for (int nt = 0; nt < 8; nt++)
                    mma16816(acc[mt][nt], a[0][mt], &b[nt >> 1][(nt & 1) * 2]);
        }
        __syncthreads();
    }

    const int g  = lane >> 2;
    const int ti = lane & 3;
#pragma unroll
    for (int mt = 0; mt < 2; mt++) {
        const int row0 = bm + warp_m * 32 + mt * 16 + g;
#pragma unroll
        for (int nt = 0; nt < 8; nt++) {
            const int col = bn + warp_n * 64 + nt * 8 + ti * 2;
            *(float2*)(Cw + (size_t)row0 * HID + col) =
                make_float2(acc[mt][nt][0], acc[mt][nt][1]);
            *(float2*)(Cw + (size_t)(row0 + 8) * HID + col) =
                make_float2(acc[mt][nt][2], acc[mt][nt][3]);
        }
    }
}

// out += partial
__global__ __launch_bounds__(256) void add_f4(
    float* __restrict__ o, const float* __restrict__ p, int n4)
{
    int i = blockIdx.x * blockDim.x + threadIdx.x;
    if (i >= n4) return;
    float4 a = ((float4*)o)[i];
    float4 b = ((const float4*)p)[i];
    a.x += b.x; a.y += b.y; a.z += b.z; a.w += b.w;
    ((float4*)o)[i] = a;
}

// ---------------------------------------------------------------------------
// HMMA bf16x3 causal flash attention. Grid (16, 28), 256 thr.
// ---------------------------------------------------------------------------
#define APITCH 272
#define QHALF  34816
#define KVSTG  69632
#define ATTN_SMEM_BYTES (QHALF * 2 + KVSTG * 2)   // 208896

__global__ __launch_bounds__(256, 1) void attn_hmma(
    const __nv_bfloat16* __restrict__ qh_, const __nv_bfloat16* __restrict__ ql_,
    const __nv_bfloat16* __restrict__ kh_, const __nv_bfloat16* __restrict__ kl_,
    const __nv_bfloat16* __restrict__ vh_, const __nv_bfloat16* __restrict__ vl_,
    __nv_bfloat16* __restrict__ aoh, __nv_bfloat16* __restrict__ aol)
{
    extern __shared__ __align__(128) char smem[];
    const uint32_t sb = smem_u32(smem);
    const int tid  = threadIdx.x;
    const int wid  = tid >> 5;
    const int lane = tid & 31;
    const int qb = gridDim.x - 1 - blockIdx.x;     // big tiles first
    const int h  = blockIdx.y;
    const int kvh = h / N_REP;
    const int q0 = qb * 128;
    const int m0 = wid * 16;
    const int nkt = 2 * qb + 2;
    const float kscale = 0.08838834764831845f * 1.4426950408889634f;

#pragma unroll
    for (int it = 0; it < 16; ++it) {
        int idx = it * 256 + tid;
        int half = idx >> 11, rem = idx & 2047;
        int r = rem >> 4, c = rem & 15;
        const __nv_bfloat16* src =
            (half ? ql_ : qh_) + (size_t)(q0 + r) * HID + h * DH + c * 8;
        cp_async16(sb + half * QHALF + r * APITCH + c * 16, src);
    }
    cp_commit();

    auto load_kv = [&](int s, int kt) {
        const int k0 = kt * 64;
        const __nv_bfloat16* srcs[4] = {kh_, kl_, vh_, vl_};
#pragma unroll
        for (int it = 0; it < 16; ++it) {
            int idx = it * 256 + tid;
            int tz = idx >> 10, rem = idx & 1023;
            int r = rem >> 4, c = rem & 15;
            const __nv_bfloat16* src =
                srcs[tz] + (size_t)(k0 + r) * DKV + kvh * DH + c * 8;
            cp_async16(sb + 2 * QHALF + s * KVSTG + tz * 17408 + r * APITCH + c * 16,
                       src);
        }
        cp_commit();
    };
    load_kv(0, 0);

    float oacc[16][4];
#pragma unroll
    for (int f = 0; f < 16; f++)
#pragma unroll
        for (int e = 0; e < 4; e++) oacc[f][e] = 0.0f;
    float m_lo = -1e30f, m_hi = -1e30f, l_lo = 0.0f, l_hi = 0.0f;

    const uint32_t a_q   = sb + (uint32_t)(m0 + (lane & 15)) * APITCH
                         + ((lane >> 4) << 4);
    const uint32_t bkrow = ((lane >> 4) << 3) + (lane & 7);
    const uint32_t bkoff = (((lane >> 3) & 1) << 4);
    const uint32_t vrow  = (lane & 15);
    const uint32_t vcoff = ((lane >> 4) << 4);
    const int row_off  = lane >> 2;
    const int col_base = (lane & 3) * 2;
    const int row_lo_g = q0 + m0 + row_off;
    const int row_hi_g = row_lo_g + 8;

    for (int kt = 0; kt < nkt; ++kt) {
        const int s  = kt & 1;
        const int k0 = kt * 64;
        if (kt + 1 < nkt) {
            load_kv(s ^ 1, kt + 1);
            asm volatile("cp.async.wait_group 1;" ::: "memory");
        } else {
            asm volatile("cp.async.wait_group 0;" ::: "memory");
        }
        __syncthreads();

        const uint32_t kvb = sb + 2 * QHALF + s * KVSTG;
        const uint32_t khb = kvb, klb = kvb + 17408;
        const uint32_t vhb = kvb + 34816, vlb = kvb + 52224;

        float sacc[8][4];
#pragma unroll
        for (int f = 0; f < 8; f++)
#pragma unroll
            for (int e = 0; e < 4; e++) sacc[f][e] = 0.0f;

#pragma unroll
        for (int k16 = 0; k16 < 8; k16++) {
            uint32_t ah[4], al[4], bt[4];
            ldsm4(ah, a_q + k16 * 32);
            ldsm4(al, a_q + QHALF + k16 * 32);
#pragma unroll
            for (int g = 0; g < 4; g++) {
                const uint32_t baddr =
                    (uint32_t)(16 * g + bkrow) * APITCH + bkoff + k16 * 32;
                ldsm4(bt, khb + baddr);
                mma16816(sacc[2 * g],     ah, bt);
                mma16816(sacc[2 * g + 1], ah, bt + 2);
                mma16816(sacc[2 * g],     al, bt);
                mma16816(sacc[2 * g + 1], al, bt + 2);
                ldsm4(bt, klb + baddr);
                mma16816(sacc[2 * g],     ah, bt);
                mma16816(sacc[2 * g + 1], ah, bt + 2);
            }
        }

        const bool flag = (k0 + 63 > q0);
        float tmx_lo = -1e30f, tmx_hi = -1e30f;
#pragma unroll
        for (int f = 0; f < 8; f++) {
            const int c0g = k0 + 8 * f + col_base;
#pragma unroll
            for (int j = 0; j < 2; j++) {
                float x = sacc[f][j] * kscale;
                if (flag && (c0g + j > row_lo_g)) x = -1e30f;
                sacc[f][j] = x;
                tmx_lo = fmaxf(tmx_lo, x);
                float y = sacc[f][j + 2] * kscale;
                if (flag && (c0g + j > row_hi_g)) y = -1e30f;
                sacc[f][j + 2] = y;
                tmx_hi = fmaxf(tmx_hi, y);
            }
        }
        tmx_lo = fmaxf(tmx_lo, __shfl_xor_sync(0xffffffffu, tmx_lo, 1));
        tmx_lo = fmaxf(tmx_lo, __shfl_xor_sync(0xffffffffu, tmx_lo, 2));
        tmx_hi = fmaxf(tmx_hi, __shfl_xor_sync(0xffffffffu, tmx_hi, 1));
        tmx_hi = fmaxf(tmx_hi, __shfl_xor_sync(0xffffffffu, tmx_hi, 2));

        const float mn_lo = fmaxf(m_lo, tmx_lo);
        const float mn_hi = fmaxf(m_hi, tmx_hi);
        const float al_lo = ex2f(m_lo - mn_lo);
        const float al_hi = ex2f(m_hi - mn_hi);
        m_lo = mn_lo; m_hi = mn_hi;

        uint32_t Ph[16], Pl[16];
        float ps_lo = 0.0f, ps_hi = 0.0f;
#pragma unroll
        for (int f = 0; f < 8; f++) {
            float p0 = ex2f(sacc[f][0] - m_lo);
            float p1 = ex2f(sacc[f][1] - m_lo);
            float p2 = ex2f(sacc[f][2] - m_hi);
            float p3 = ex2f(sacc[f][3] - m_hi);
            ps_lo += p0 + p1; ps_hi += p2 + p3;
            const int c  = f >> 1;
            const int rb = (f & 1) * 2;
            split2(p0, p1, Ph[c * 4 + rb],     Pl[c * 4 + rb]);
            split2(p2, p3, Ph[c * 4 + rb + 1], Pl[c * 4 + rb + 1]);
        }
        ps_lo += __shfl_xor_sync(0xffffffffu, ps_lo, 1);
        ps_lo += __shfl_xor_sync(0xffffffffu, ps_lo, 2);
        ps_hi += __shfl_xor_sync(0xffffffffu, ps_hi, 1);
        ps_hi += __shfl_xor_sync(0xffffffffu, ps_hi, 2);
        l_lo = l_lo * al_lo + ps_lo;
        l_hi = l_hi * al_hi + ps_hi;

#pragma unroll
        for (int f = 0; f < 16; f++) {
            oacc[f][0] *= al_lo; oacc[f][1] *= al_lo;
            oacc[f][2] *= al_hi; oacc[f][3] *= al_hi;
        }

#pragma unroll
        for (int c = 0; c < 4; c++) {
#pragma unroll
            for (int g = 0; g < 8; g++) {
                const uint32_t baddr =
                    (uint32_t)(16 * c + vrow) * APITCH + 32 * g + vcoff;
                uint32_t bt[4];
                ldsm4t(bt, vhb + baddr);
                mma16816(oacc[2 * g],     &Ph[c * 4], bt);
                mma16816(oacc[2 * g + 1], &Ph[c * 4], bt + 2);
                mma16816(oacc[2 * g],     &Pl[c * 4], bt);
                mma16816(oacc[2 * g + 1], &Pl[c * 4], bt + 2);
                ldsm4t(bt, vlb + baddr);
                mma16816(oacc[2 * g],     &Ph[c * 4], bt);
                mma16816(oacc[2 * g + 1], &Ph[c * 4], bt + 2);
            }
        }
        __syncthreads();
    }

    // ---- normalize + direct hi/lo bf16 store ----
    const float inv_lo = 1.0f / l_lo;
    const float inv_hi = 1.0f / l_hi;
#pragma unroll
    for (int f = 0; f < 16; f++) {
        const int col = 8 * f + col_base;
        const size_t off_lo = (size_t)row_lo_g * HID + h * DH + col;
        const size_t off_hi = (size_t)row_hi_g * HID + h * DH + col;
        uint32_t h0, l0, h1, l1;
        split2(oacc[f][0] * inv_lo, oacc[f][1] * inv_lo, h0, l0);
        split2(oacc[f][2] * inv_hi, oacc[f][3] * inv_hi, h1, l1);
        *(uint32_t*)(aoh + off_lo) = h0;
        *(uint32_t*)(aoh + off_hi) = h1;
        *(uint32_t*)(aol + off_lo) = l0;
        *(uint32_t*)(aol + off_hi) = l1;
    }
}

// ---------------------------------------------------------------------------
// Launch
// ---------------------------------------------------------------------------
extern "C" void kernel_launch(void* const* d_in, const int* in_sizes, int n_in,
                              void* d_out, int out_size)
{
    const float* hs   = (const float*)d_in[0];
    const float* Wq   = (const float*)d_in[1];
    const float* bq   = (const float*)d_in[2];
    const float* Wk   = (const float*)d_in[3];
    const float* bk   = (const float*)d_in[4];
    const float* Wv   = (const float*)d_in[5];
    const float* bv   = (const float*)d_in[6];
    const float* Wo   = (const float*)d_in[7];
    const float* cosb = (const float*)d_in[8];
    const float* sinb = (const float*)d_in[9];
    float* out = (float*)d_out;

    float* P1;
    cudaGetSymbolAddress((void**)&P1, g_P1);

    __nv_bfloat16 *hsh, *hsl, *aoh, *aol, *wqh, *wql, *wkh, *wkl, *wvh, *wvl, *woh, *wol;
    __nv_bfloat16 *qh, *ql, *kh, *kl, *vh, *vl;
    cudaGetSymbolAddress((void**)&hsh, g_hs_h); cudaGetSymbolAddress((void**)&hsl, g_hs_l);
    cudaGetSymbolAddress((void**)&aoh, g_ao_h); cudaGetSymbolAddress((void**)&aol, g_ao_l);
    cudaGetSymbolAddress((void**)&wqh, g_wq_h); cudaGetSymbolAddress((void**)&wql, g_wq_l);
    cudaGetSymbolAddress((void**)&wkh, g_wk_h); cudaGetSymbolAddress((void**)&wkl, g_wk_l);
    cudaGetSymbolAddress((void**)&wvh, g_wv_h); cudaGetSymbolAddress((void**)&wvl, g_wv_l);
    cudaGetSymbolAddress((void**)&woh, g_wo_h); cudaGetSymbolAddress((void**)&wol, g_wo_l);
    cudaGetSymbolAddress((void**)&qh, g_q_h);   cudaGetSymbolAddress((void**)&ql, g_q_l);
    cudaGetSymbolAddress((void**)&kh, g_k_h);   cudaGetSymbolAddress((void**)&kl, g_k_l);
    cudaGetSymbolAddress((void**)&vh, g_v_h);   cudaGetSymbolAddress((void**)&vl, g_v_l);

    cudaFuncSetAttribute(gemm_qkv, cudaFuncAttributeMaxDynamicSharedMemorySize,
                         GEMM_SMEM_BYTES);
    cudaFuncSetAttribute(gemm_osplit, cudaFuncAttributeMaxDynamicSharedMemorySize,
                         GEMM_SMEM_BYTES);
    cudaFuncSetAttribute(attn_hmma, cudaFuncAttributeMaxDynamicSharedMemorySize,
                         ATTN_SMEM_BYTES);

    // single fused hi/lo split: grid-strided x4, coalesced + MLP=4
    split5<<<(SEG5 / 4 + 255) / 256, 256>>>(hs, Wq, Wk, Wv, Wo,
                                            hsh, hsl, wqh, wql, wkh, wkl,
                                            wvh, wvl, woh, wol);

    // fused QKV projection + RoPE: emits q/k/v hi-lo bf16 directly
    gemm_qkv<<<dim3((HID + 2 * DKV) / 128, S_LEN / 128), 256, GEMM_SMEM_BYTES>>>(
        hsh, hsl, wqh, wql, wkh, wkl, wvh, wvl, bq, bk, bv,
        cosb, sinb, qh, ql, kh, kl, vh, vl);

    attn_hmma<<<dim3(S_LEN / 128, NHQ), 256, ATTN_SMEM_BYTES>>>(
        qh, ql, kh, kl, vh, vl, aoh, aol);

    // split-K(2) O projection + reduction
    gemm_osplit<<<dim3(HID / 128, S_LEN / 128, 2), 256, GEMM_SMEM_BYTES>>>(
        aoh, aol, woh, wol, out, P1);
    add_f4<<<(S_LEN * HID / 4 + 255) / 256, 256>>>(out, P1, S_LEN * HID / 4);
}